// round 13
// baseline (speedup 1.0000x reference)
#include <cuda_runtime.h>
#include <cstdint>

#define NBOX   2048
#define NCLS   80
#define NTHR   1024
#define PC     64           // per-class box cap (P(Binom(2048,1/80)>64) ~ 1e-11)
#define ROWCAP 128          // rows per class <= 2*PC
#define VOTE_TH  0.65f
#define SOFT_THR 0.05f
#define CANDCAP  512
#define NBUCKET  1024

typedef unsigned long long u64;
typedef unsigned int u32;

__device__ float4 g_cboxes[NCLS * ROWCAP];  // compact box buffer (offset coords)
__device__ u64    g_ckeys[NCLS * ROWCAP];   // compact key buffer
__device__ int    g_hist[NBUCKET];
__device__ int    g_total = 0;
__device__ int    g_done  = 0;

// Key (ascending = output order): score desc (32b inverted float bits, exact
// & invertible), head original index asc (11b), within-cluster slot (7b),
// row ref = class*ROWCAP+slot (14b; also encodes the class/label).
__device__ __forceinline__ u64 makeKey(float score, int headIdx, int within, int ref) {
    u64 u = (u64)(0xFFFFFFFFu - __float_as_uint(score));
    return (u << 32) | ((u64)headIdx << 21) | ((u64)within << 14) | (u64)ref;
}

__device__ __forceinline__ int keyBucket(u64 k) {
    u32 inv = (u32)(k >> 32);
    int bkt = (int)((inv - 0xC0000000u) >> 16);
    return bkt > (NBUCKET - 1) ? (NBUCKET - 1) : (bkt < 0 ? 0 : bkt);
}

// Exactly replicates (__fdiv_rn(inter, u) >= VOTE_TH) without dividing in the
// common case; the +-4e-7 band covers all quotient-rounding ambiguity.
__device__ __forceinline__ bool mergePred(float inter, float u) {
    float t = VOTE_TH * u;
    if (inter > t * 1.0000006f) return true;
    if (inter < t * 0.9999994f) return false;
    return __fdiv_rn(inter, u) >= VOTE_TH;
}

__global__ __launch_bounds__(NTHR) void k_fused(const float* __restrict__ boxes,
                                                const float* __restrict__ scores,
                                                const int*   __restrict__ labels,
                                                float* __restrict__ out) {
    const int c = blockIdx.x, tid = threadIdx.x;
    const int wid = tid >> 5, lane = tid & 31;
    const unsigned FULL = 0xFFFFFFFFu;

    __shared__ float s_max[NTHR / 32];
    __shared__ int   s_n, s_pos, s_last;
    __shared__ u64   s_key[PC];      // unsorted slot order
    __shared__ float4 s_bx[PC];      // raw coords, unsorted slot order
    __shared__ u64   s_adj[PC];      // IoU>=0.65 adjacency (slot-space bits)
    __shared__ u64   s_blw[PC];      // below[r] = {j : key[j] < key[r]}
    __shared__ int   s_ch[PC];
    __shared__ u64   s_cm[PC], s_sm[PC];
    __shared__ float4 s_b0[PC];      // voted head boxes
    __shared__ int   s_rc[PC + 1];
    // selection (last block only)
    __shared__ int   s_hist[NBUCKET];
    __shared__ u64   s_cand[CANDCAP];
    __shared__ int   s_cidx[CANDCAP];
    __shared__ int   s_cut, s_ncand;

    // ---- Phase A: issue ALL global loads first (independent, one RT) ----
    const float4* b4 = (const float4*)boxes;
    float4 v0 = b4[tid];
    float4 v1 = b4[tid + NTHR];
    int   l0 = labels[tid],        l1 = labels[tid + NTHR];
    float f0 = scores[tid],        f1 = scores[tid + NTHR];

    if (tid == 0) s_n = 0;
    if (tid < PC) { s_adj[tid] = 0; s_blw[tid] = 0; s_cm[tid] = 0; }
    __syncthreads();

    float m = fmaxf(fmaxf(fmaxf(v0.x, v0.y), fmaxf(v0.z, v0.w)),
                    fmaxf(fmaxf(v1.x, v1.y), fmaxf(v1.z, v1.w)));
    if (l0 == c) { int p = atomicAdd(&s_n, 1); if (p < PC) { s_key[p] = ((u64)(0xFFFFFFFFu - __float_as_uint(f0)) << 32) | (u32)tid;          s_bx[p] = v0; } }
    if (l1 == c) { int p = atomicAdd(&s_n, 1); if (p < PC) { s_key[p] = ((u64)(0xFFFFFFFFu - __float_as_uint(f1)) << 32) | (u32)(tid + NTHR); s_bx[p] = v1; } }

    for (int o = 16; o; o >>= 1) m = fmaxf(m, __shfl_xor_sync(FULL, m, o));
    if (lane == 0) s_max[wid] = m;
    __syncthreads();

    float mc = s_max[0];
#pragma unroll
    for (int w = 1; w < NTHR / 32; w++) mc = fmaxf(mc, s_max[w]);
    mc += 1.0f;   // exact max -> identical in every block

    const int n = (s_n > PC) ? PC : s_n;
    const float off = (float)c * mc;

    // ---- Phase C': fused adjacency + below-mask, 16 threads per row ----
    {
        int r = tid >> 4, q = tid & 15;
        if (r < n) {
            u64 kr = s_key[r];
            float4 br = s_bx[r];
            float rx1 = br.x + off, ry1 = br.y + off, rx2 = br.z + off, ry2 = br.w + off;
            float ra = (rx2 - rx1) * (ry2 - ry1);
            int j0 = q * 4, j1 = j0 + 4; if (j1 > n) j1 = n;
            u64 abits = 0, bbits = 0;
            for (int j = j0; j < j1; j++) {
                u64 kj = s_key[j];
                float4 bj = s_bx[j];
                float jx1 = bj.x + off, jy1 = bj.y + off, jx2 = bj.z + off, jy2 = bj.w + off;
                float xx1 = fmaxf(rx1, jx1);
                float yy1 = fmaxf(ry1, jy1);
                float xx2 = fminf(rx2, jx2);
                float yy2 = fminf(ry2, jy2);
                float inter = fmaxf(xx2 - xx1, 0.f) * fmaxf(yy2 - yy1, 0.f);
                float ua = ra + (jx2 - jx1) * (jy2 - jy1) - inter;
                if (mergePred(inter, ua)) abits |= 1ull << j;
                if (kj < kr)              bbits |= 1ull << j;
            }
            if (abits) atomicOr(&s_adj[r], abits);
            if (bbits) atomicOr(&s_blw[r], bbits);
        }
    }
    __syncthreads();

    // ======== Phases D..G entirely in warp 0 (2 rows / 2 clusters per lane) ====
    if (wid == 0) {
        const int r0i = lane, r1i = lane + 32;
        u64 a0 = s_adj[r0i], a1 = s_adj[r1i];
        u64 bl0 = s_blw[r0i], bl1 = s_blw[r1i];
        const u64 validMask = (n >= 64) ? ~0ull : ((1ull << n) - 1ull);
        const bool val0 = r0i < n, val1 = r1i < n;

        // ---- D1: fixpoint head-set iteration (key-order below masks) ----
        u64 head = validMask;
        for (int it = 0; it < 64; it++) {
            bool b0 = val0 && ((a0 & head & bl0) == 0);
            bool b1 = val1 && ((a1 & head & bl1) == 0);
            u64 nh = (u64)__ballot_sync(FULL, b0) | ((u64)__ballot_sync(FULL, b1) << 32);
            if (nh == head) break;
            head = nh;
        }

        // ---- D2: cluster assignment (owner = argmin-key adjacent head) ----
#pragma unroll
        for (int e = 0; e < 2; e++) {
            int r = lane + e * 32;
            if (r < n) {
                u64 cand = (e ? a1 : a0) & head;   // nonempty (self-adjacency)
                int h = __ffsll((long long)cand) - 1;
                u64 bk = s_key[h];
                u64 t2 = cand & (cand - 1);
                while (t2) {
                    int j = __ffsll((long long)t2) - 1; t2 &= t2 - 1;
                    u64 kj = s_key[j];
                    if (kj < bk) { bk = kj; h = j; }
                }
                int ci = __popcll(head & s_blw[h]);  // clusters in key order
                atomicOr(&s_cm[ci], 1ull << r);
                if (h == r) s_ch[ci] = r;
            }
        }
        const int ncl = __popcll(head);
        __syncwarp();

        // ---- E: per-cluster head row + soft mask/count (2 clusters per lane) ----
        float hsA[2];
#pragma unroll
        for (int e = 0; e < 2; e++) {
            int ci = lane + e * 32;
            if (ci < ncl) {
                int h = s_ch[ci];
                u64 mg = s_cm[ci];
                int nm = __popcll(mg);
                hsA[e] = __uint_as_float(0xFFFFFFFFu - (u32)(s_key[h] >> 32));

                float wsum = 0.f, w0 = 0.f, w1 = 0.f, w2 = 0.f, w3 = 0.f;
                u64 mm = mg;
                while (mm) {
                    int t = __ffsll((long long)mm) - 1; mm &= mm - 1;
                    float sv = __uint_as_float(0xFFFFFFFFu - (u32)(s_key[t] >> 32));
                    float4 bt = s_bx[t];
                    wsum += sv;
                    w0 += (bt.x + off) * sv; w1 += (bt.y + off) * sv;
                    w2 += (bt.z + off) * sv; w3 += (bt.w + off) * sv;
                }
                float wsafe = (wsum > 0.f) ? wsum : 1.f;
                s_b0[ci] = make_float4(__fdiv_rn(w0, wsafe), __fdiv_rn(w1, wsafe),
                                       __fdiv_rn(w2, wsafe), __fdiv_rn(w3, wsafe));

                u64 soft = 0; int cnt = 1;
                if (nm > 1) {
                    float4 bh = s_bx[h];
                    float hx1 = bh.x + off, hy1 = bh.y + off, hx2 = bh.z + off, hy2 = bh.w + off;
                    float ha = (hx2 - hx1) * (hy2 - hy1);
                    mm = mg;
                    while (mm) {
                        int t = __ffsll((long long)mm) - 1; mm &= mm - 1;
                        float4 bt = s_bx[t];
                        float tx1 = bt.x + off, ty1 = bt.y + off, tx2 = bt.z + off, ty2 = bt.w + off;
                        float xx1 = fmaxf(hx1, tx1);
                        float yy1 = fmaxf(hy1, ty1);
                        float xx2 = fminf(hx2, tx2);
                        float yy2 = fminf(hy2, ty2);
                        float inter = fmaxf(xx2 - xx1, 0.f) * fmaxf(yy2 - yy1, 0.f);
                        float iou = __fdiv_rn(inter, ha + (tx2 - tx1) * (ty2 - ty1) - inter);
                        float sv = __uint_as_float(0xFFFFFFFFu - (u32)(s_key[t] >> 32));
                        float sfs = sv * (1.0f - iou);
                        if (sfs >= SOFT_THR) { soft |= 1ull << t; cnt++; }
                    }
                }
                s_sm[ci] = soft;
                s_rc[ci] = cnt;
            }
        }
        __syncwarp();

        // ---- F: warp exclusive scan of cluster row counts + global append pos ----
        {
            int v0i = (lane < ncl) ? s_rc[lane] : 0;
            int v1i = (lane + 32 < ncl) ? s_rc[lane + 32] : 0;
            int sa0 = v0i, sa1 = v1i;
            for (int o = 1; o < 32; o <<= 1) {
                int t = __shfl_up_sync(FULL, sa0, o); if (lane >= o) sa0 += t;
                int u = __shfl_up_sync(FULL, sa1, o); if (lane >= o) sa1 += u;
            }
            int tot0 = __shfl_sync(FULL, sa0, 31);
            int tot  = tot0 + __shfl_sync(FULL, sa1, 31);
            if (lane < ncl) s_rc[lane] = sa0 - v0i;
            if (lane + 32 < ncl) s_rc[lane + 32] = tot0 + sa1 - v1i;
            if (lane == 0) s_pos = atomicAdd(&g_total, tot);
        }
        __syncwarp();
        const int posG = s_pos;

        // ---- G: parallel emission of boxes + keys + global histogram ----
#pragma unroll
        for (int e = 0; e < 2; e++) {
            int ci = lane + e * 32;
            if (ci < ncl) {
                int h = s_ch[ci];
                int hoi = (int)(s_key[h] & 0x7FFull);
                int ofs = s_rc[ci];
                int slot = c * ROWCAP + ofs;
                g_cboxes[posG + ofs] = s_b0[ci];
                u64 hk = makeKey(hsA[e], hoi, 0, slot);
                g_ckeys[posG + ofs] = hk;
                atomicAdd(&g_hist[keyBucket(hk)], 1);

                u64 mm = s_sm[ci];
                if (mm) {
                    float4 bh = s_bx[h];
                    float hx1 = bh.x + off, hy1 = bh.y + off, hx2 = bh.z + off, hy2 = bh.w + off;
                    float ha = (hx2 - hx1) * (hy2 - hy1);
                    int w = ofs + 1;
                    while (mm) {
                        int t = __ffsll((long long)mm) - 1; mm &= mm - 1;
                        float4 bt = s_bx[t];
                        float tx1 = bt.x + off, ty1 = bt.y + off, tx2 = bt.z + off, ty2 = bt.w + off;
                        float xx1 = fmaxf(hx1, tx1);
                        float yy1 = fmaxf(hy1, ty1);
                        float xx2 = fminf(hx2, tx2);
                        float yy2 = fminf(hy2, ty2);
                        float inter = fmaxf(xx2 - xx1, 0.f) * fmaxf(yy2 - yy1, 0.f);
                        float iou = __fdiv_rn(inter, ha + (tx2 - tx1) * (ty2 - ty1) - inter);
                        float sv = __uint_as_float(0xFFFFFFFFu - (u32)(s_key[t] >> 32));
                        float sfs = sv * (1.0f - iou);
                        g_cboxes[posG + w] = make_float4(tx1, ty1, tx2, ty2);
                        u64 sk = makeKey(sfs, hoi, t + 1, c * ROWCAP + w);
                        g_ckeys[posG + w] = sk;
                        atomicAdd(&g_hist[keyBucket(sk)], 1);
                        w++;
                    }
                }
            }
        }
        __threadfence();     // release: only warp 0 wrote globals
    }

    // ---- last-block-done ----
    __syncthreads();
    if (tid == 0) {
        int d = atomicAdd(&g_done, 1);
        s_last = (d == NCLS - 1);
    }
    __syncthreads();
    if (!s_last) return;
    __threadfence();   // acquire

    // ================= selection (one block, 1024 threads) =================
    int nt = *((volatile int*)&g_total);

    if (tid < NBUCKET) s_hist[tid] = g_hist[tid];
    if (tid == 0) { s_ncand = 0; s_cut = NBUCKET - 1; }
    __syncthreads();

    if (wid == 0) {    // scores < 1.0 -> bucket >= 127 -> start at group 3
        int acc = 0;
        for (int g = 3; g < NBUCKET / 32; g++) {
            int v = s_hist[g * 32 + lane];
            int scn = v;
            for (int o = 1; o < 32; o <<= 1) {
                int t = __shfl_up_sync(FULL, scn, o);
                if (lane >= o) scn += t;
            }
            unsigned bal = __ballot_sync(FULL, acc + scn >= 100);
            if (bal) { if (lane == 0) s_cut = g * 32 + __ffs(bal) - 1; break; }
            acc += __shfl_sync(FULL, scn, 31);
        }
    }
    __syncthreads();
    const int B = s_cut;

    // collect candidates with warp-aggregated append
    {
        int rounds = (nt + NTHR - 1) / NTHR;
        for (int r = 0; r < rounds; r++) {
            int i = tid + r * NTHR;
            u64 k = 0;
            bool pred = false;
            if (i < nt) {
                k = g_ckeys[i];
                pred = (keyBucket(k) <= B);
            }
            unsigned msk = __ballot_sync(FULL, pred);
            if (msk) {
                int leader = __ffs(msk) - 1;
                int base = 0;
                if (lane == leader) base = atomicAdd(&s_ncand, __popc(msk));
                base = __shfl_sync(FULL, base, leader);
                if (pred) {
                    int p = base + __popc(msk & ((1u << lane) - 1u));
                    if (p < CANDCAP) { s_cand[p] = k; s_cidx[p] = i; }
                }
            }
        }
    }
    __syncthreads();
    int nc = s_ncand; if (nc > CANDCAP) nc = CANDCAP;

    // fused rank-compute -> direct output (ranks are a bijection 0..nc-1)
    if (tid < nc) {
        u64 k = s_cand[tid];
        int rank = 0;
        for (int j = 0; j < nc; j++) rank += (s_cand[j] < k);
        if (rank < 100) {
            int ref = (int)(k & 0x3FFFull);
            float lb = (float)(ref / ROWCAP);                          // exact label
            float scr = __uint_as_float(0xFFFFFFFFu - (u32)(k >> 32)); // exact score
            float4 bx = g_cboxes[s_cidx[tid]];
            float o2 = lb * mc;
            out[rank * 4 + 0] = bx.x - o2;
            out[rank * 4 + 1] = bx.y - o2;
            out[rank * 4 + 2] = bx.z - o2;
            out[rank * 4 + 3] = bx.w - o2;
            out[400 + rank] = scr;
            out[500 + rank] = lb;
        }
    } else if (tid < 100) {      // ranks that cannot exist: zero-fill
        out[tid * 4 + 0] = 0.f; out[tid * 4 + 1] = 0.f;
        out[tid * 4 + 2] = 0.f; out[tid * 4 + 3] = 0.f;
        out[400 + tid] = 0.f;
        out[500 + tid] = 0.f;
    }

    // reset globals for next graph replay
    if (tid < NBUCKET) g_hist[tid] = 0;
    __syncthreads();
    if (tid == 0) { g_total = 0; g_done = 0; }
}

extern "C" void kernel_launch(void* const* d_in, const int* in_sizes, int n_in,
                              void* d_out, int out_size) {
    const float* boxes  = (const float*)d_in[0];
    const float* scores = (const float*)d_in[1];
    const int*   labels = (const int*)d_in[2];
    float* out = (float*)d_out;

    k_fused<<<NCLS, NTHR>>>(boxes, scores, labels, out);
}

// round 15
// speedup vs baseline: 1.0175x; 1.0175x over previous
#include <cuda_runtime.h>
#include <cstdint>

#define NBOX   2048
#define NCLS   80
#define NTHR   1024
#define PC     64           // per-class box cap (P(Binom(2048,1/80)>64) ~ 1e-11)
#define ROWCAP 128          // rows per class <= 2*PC
#define VOTE_TH  0.65f
#define SOFT_THR 0.05f
#define CANDCAP  512
#define NBUCKET  1024
#define KCAP   2048         // tail smem key-prefetch capacity

typedef unsigned long long u64;
typedef unsigned int u32;

__device__ float4 g_cboxes[NCLS * ROWCAP];  // compact box buffer (offset coords)
__device__ u64    g_ckeys[NCLS * ROWCAP];   // compact key buffer
__device__ int    g_total = 0;              // row allocator
__device__ u64    g_doneTotal = 0;          // (blocks_done << 40) | rows_done

// Key (ascending = output order): score desc (32b inverted float bits, exact
// & invertible), head original index asc (11b), within-cluster slot (7b),
// row ref = class*ROWCAP+slot (14b; also encodes the class/label).
__device__ __forceinline__ u64 makeKey(float score, int headIdx, int within, int ref) {
    u64 u = (u64)(0xFFFFFFFFu - __float_as_uint(score));
    return (u << 32) | ((u64)headIdx << 21) | ((u64)within << 14) | (u64)ref;
}

__device__ __forceinline__ int keyBucket(u64 k) {
    u32 inv = (u32)(k >> 32);
    int bkt = (int)((inv - 0xC0000000u) >> 16);
    return bkt > (NBUCKET - 1) ? (NBUCKET - 1) : (bkt < 0 ? 0 : bkt);
}

// Exactly replicates (__fdiv_rn(inter, u) >= VOTE_TH) without dividing in the
// common case; the +-4e-7 band covers all quotient-rounding ambiguity.
__device__ __forceinline__ bool mergePred(float inter, float u) {
    float t = VOTE_TH * u;
    if (inter > t * 1.0000006f) return true;
    if (inter < t * 0.9999994f) return false;
    return __fdiv_rn(inter, u) >= VOTE_TH;
}

__global__ __launch_bounds__(NTHR) void k_fused(const float* __restrict__ boxes,
                                                const float* __restrict__ scores,
                                                const int*   __restrict__ labels,
                                                float* __restrict__ out) {
    const int c = blockIdx.x, tid = threadIdx.x;
    const int wid = tid >> 5, lane = tid & 31;
    const unsigned FULL = 0xFFFFFFFFu;

    __shared__ float s_max[NTHR / 32];
    __shared__ int   s_n, s_pos, s_last, s_nt;
    __shared__ u64   s_key[PC];      // unsorted slot order
    __shared__ float4 s_bx[PC];      // raw coords, unsorted slot order
    __shared__ u64   s_adj[PC];      // IoU>=0.65 adjacency (slot-space bits)
    __shared__ u64   s_blw[PC];      // below[r] = {j : key[j] < key[r]}
    __shared__ int   s_ch[PC];
    __shared__ u64   s_cm[PC], s_sm[PC];
    __shared__ float4 s_b0[PC];      // voted head boxes
    __shared__ int   s_rc[PC + 1];
    // selection (last block only)
    __shared__ int   s_hist[NBUCKET];
    __shared__ u64   s_tkeys[KCAP];
    __shared__ u64   s_cand[CANDCAP];
    __shared__ int   s_cidx[CANDCAP];
    __shared__ int   s_cut, s_ncand;

    // ---- Phase A: issue ALL global loads first (independent, one RT) ----
    const float4* b4 = (const float4*)boxes;
    float4 v0 = b4[tid];
    float4 v1 = b4[tid + NTHR];
    int   l0 = labels[tid],        l1 = labels[tid + NTHR];
    float f0 = scores[tid],        f1 = scores[tid + NTHR];

    if (tid == 0) s_n = 0;
    if (tid < PC) { s_adj[tid] = 0; s_blw[tid] = 0; s_cm[tid] = 0; }
    __syncthreads();

    float m = fmaxf(fmaxf(fmaxf(v0.x, v0.y), fmaxf(v0.z, v0.w)),
                    fmaxf(fmaxf(v1.x, v1.y), fmaxf(v1.z, v1.w)));
    if (l0 == c) { int p = atomicAdd(&s_n, 1); if (p < PC) { s_key[p] = ((u64)(0xFFFFFFFFu - __float_as_uint(f0)) << 32) | (u32)tid;          s_bx[p] = v0; } }
    if (l1 == c) { int p = atomicAdd(&s_n, 1); if (p < PC) { s_key[p] = ((u64)(0xFFFFFFFFu - __float_as_uint(f1)) << 32) | (u32)(tid + NTHR); s_bx[p] = v1; } }

    for (int o = 16; o; o >>= 1) m = fmaxf(m, __shfl_xor_sync(FULL, m, o));
    if (lane == 0) s_max[wid] = m;
    __syncthreads();

    float mc = s_max[0];
#pragma unroll
    for (int w = 1; w < NTHR / 32; w++) mc = fmaxf(mc, s_max[w]);
    mc += 1.0f;   // exact max -> identical in every block

    const int n = (s_n > PC) ? PC : s_n;
    const float off = (float)c * mc;

    // ---- Phase C': fused adjacency + below-mask, 16 threads per row ----
    {
        int r = tid >> 4, q = tid & 15;
        if (r < n) {
            u64 kr = s_key[r];
            float4 br = s_bx[r];
            float rx1 = br.x + off, ry1 = br.y + off, rx2 = br.z + off, ry2 = br.w + off;
            float ra = (rx2 - rx1) * (ry2 - ry1);
            int j0 = q * 4, j1 = j0 + 4; if (j1 > n) j1 = n;
            u64 abits = 0, bbits = 0;
            for (int j = j0; j < j1; j++) {
                u64 kj = s_key[j];
                float4 bj = s_bx[j];
                float jx1 = bj.x + off, jy1 = bj.y + off, jx2 = bj.z + off, jy2 = bj.w + off;
                float xx1 = fmaxf(rx1, jx1);
                float yy1 = fmaxf(ry1, jy1);
                float xx2 = fminf(rx2, jx2);
                float yy2 = fminf(ry2, jy2);
                float inter = fmaxf(xx2 - xx1, 0.f) * fmaxf(yy2 - yy1, 0.f);
                float ua = ra + (jx2 - jx1) * (jy2 - jy1) - inter;
                if (mergePred(inter, ua)) abits |= 1ull << j;
                if (kj < kr)              bbits |= 1ull << j;
            }
            if (abits) atomicOr(&s_adj[r], abits);
            if (bbits) atomicOr(&s_blw[r], bbits);
        }
    }
    __syncthreads();

    // ======== Phases D..G entirely in warp 0 (2 rows / 2 clusters per lane) ====
    int myTot = 0;
    if (wid == 0) {
        const int r0i = lane, r1i = lane + 32;
        u64 a0 = s_adj[r0i], a1 = s_adj[r1i];
        u64 bl0 = s_blw[r0i], bl1 = s_blw[r1i];
        const u64 validMask = (n >= 64) ? ~0ull : ((1ull << n) - 1ull);
        const bool val0 = r0i < n, val1 = r1i < n;

        // ---- D1: fixpoint head-set iteration (key-order below masks) ----
        u64 head = validMask;
        for (int it = 0; it < 64; it++) {
            bool b0 = val0 && ((a0 & head & bl0) == 0);
            bool b1 = val1 && ((a1 & head & bl1) == 0);
            u64 nh = (u64)__ballot_sync(FULL, b0) | ((u64)__ballot_sync(FULL, b1) << 32);
            if (nh == head) break;
            head = nh;
        }

        // ---- D2: cluster assignment (owner = argmin-key adjacent head) ----
#pragma unroll
        for (int e = 0; e < 2; e++) {
            int r = lane + e * 32;
            if (r < n) {
                u64 cand = (e ? a1 : a0) & head;   // nonempty (self-adjacency)
                int h = __ffsll((long long)cand) - 1;
                u64 bk = s_key[h];
                u64 t2 = cand & (cand - 1);
                while (t2) {
                    int j = __ffsll((long long)t2) - 1; t2 &= t2 - 1;
                    u64 kj = s_key[j];
                    if (kj < bk) { bk = kj; h = j; }
                }
                int ci = __popcll(head & s_blw[h]);  // clusters in key order
                atomicOr(&s_cm[ci], 1ull << r);
                if (h == r) s_ch[ci] = r;
            }
        }
        const int ncl = __popcll(head);
        __syncwarp();

        // ---- E: per-cluster head row + soft mask/count (2 clusters per lane) ----
        float hsA[2];
#pragma unroll
        for (int e = 0; e < 2; e++) {
            int ci = lane + e * 32;
            if (ci < ncl) {
                int h = s_ch[ci];
                u64 mg = s_cm[ci];
                int nm = __popcll(mg);
                hsA[e] = __uint_as_float(0xFFFFFFFFu - (u32)(s_key[h] >> 32));

                float wsum = 0.f, w0 = 0.f, w1 = 0.f, w2 = 0.f, w3 = 0.f;
                u64 mm = mg;
                while (mm) {
                    int t = __ffsll((long long)mm) - 1; mm &= mm - 1;
                    float sv = __uint_as_float(0xFFFFFFFFu - (u32)(s_key[t] >> 32));
                    float4 bt = s_bx[t];
                    wsum += sv;
                    w0 += (bt.x + off) * sv; w1 += (bt.y + off) * sv;
                    w2 += (bt.z + off) * sv; w3 += (bt.w + off) * sv;
                }
                float wsafe = (wsum > 0.f) ? wsum : 1.f;
                s_b0[ci] = make_float4(__fdiv_rn(w0, wsafe), __fdiv_rn(w1, wsafe),
                                       __fdiv_rn(w2, wsafe), __fdiv_rn(w3, wsafe));

                u64 soft = 0; int cnt = 1;
                if (nm > 1) {
                    float4 bh = s_bx[h];
                    float hx1 = bh.x + off, hy1 = bh.y + off, hx2 = bh.z + off, hy2 = bh.w + off;
                    float ha = (hx2 - hx1) * (hy2 - hy1);
                    mm = mg;
                    while (mm) {
                        int t = __ffsll((long long)mm) - 1; mm &= mm - 1;
                        float4 bt = s_bx[t];
                        float tx1 = bt.x + off, ty1 = bt.y + off, tx2 = bt.z + off, ty2 = bt.w + off;
                        float xx1 = fmaxf(hx1, tx1);
                        float yy1 = fmaxf(hy1, ty1);
                        float xx2 = fminf(hx2, tx2);
                        float yy2 = fminf(hy2, ty2);
                        float inter = fmaxf(xx2 - xx1, 0.f) * fmaxf(yy2 - yy1, 0.f);
                        float iou = __fdiv_rn(inter, ha + (tx2 - tx1) * (ty2 - ty1) - inter);
                        float sv = __uint_as_float(0xFFFFFFFFu - (u32)(s_key[t] >> 32));
                        float sfs = sv * (1.0f - iou);
                        if (sfs >= SOFT_THR) { soft |= 1ull << t; cnt++; }
                    }
                }
                s_sm[ci] = soft;
                s_rc[ci] = cnt;
            }
        }
        __syncwarp();

        // ---- F: warp exclusive scan of cluster row counts + global append pos ----
        {
            int v0i = (lane < ncl) ? s_rc[lane] : 0;
            int v1i = (lane + 32 < ncl) ? s_rc[lane + 32] : 0;
            int sa0 = v0i, sa1 = v1i;
            for (int o = 1; o < 32; o <<= 1) {
                int t = __shfl_up_sync(FULL, sa0, o); if (lane >= o) sa0 += t;
                int u = __shfl_up_sync(FULL, sa1, o); if (lane >= o) sa1 += u;
            }
            int tot0 = __shfl_sync(FULL, sa0, 31);
            int tot  = tot0 + __shfl_sync(FULL, sa1, 31);
            if (lane < ncl) s_rc[lane] = sa0 - v0i;
            if (lane + 32 < ncl) s_rc[lane + 32] = tot0 + sa1 - v1i;
            if (lane == 0) { s_pos = atomicAdd(&g_total, tot); myTot = tot; }
        }
        __syncwarp();
        const int posG = s_pos;

        // ---- G: parallel emission of boxes + keys ----
#pragma unroll
        for (int e = 0; e < 2; e++) {
            int ci = lane + e * 32;
            if (ci < ncl) {
                int h = s_ch[ci];
                int hoi = (int)(s_key[h] & 0x7FFull);
                int ofs = s_rc[ci];
                int slot = c * ROWCAP + ofs;
                g_cboxes[posG + ofs] = s_b0[ci];
                g_ckeys[posG + ofs] = makeKey(hsA[e], hoi, 0, slot);

                u64 mm = s_sm[ci];
                if (mm) {
                    float4 bh = s_bx[h];
                    float hx1 = bh.x + off, hy1 = bh.y + off, hx2 = bh.z + off, hy2 = bh.w + off;
                    float ha = (hx2 - hx1) * (hy2 - hy1);
                    int w = ofs + 1;
                    while (mm) {
                        int t = __ffsll((long long)mm) - 1; mm &= mm - 1;
                        float4 bt = s_bx[t];
                        float tx1 = bt.x + off, ty1 = bt.y + off, tx2 = bt.z + off, ty2 = bt.w + off;
                        float xx1 = fmaxf(hx1, tx1);
                        float yy1 = fmaxf(hy1, ty1);
                        float xx2 = fminf(hx2, tx2);
                        float yy2 = fminf(hy2, ty2);
                        float inter = fmaxf(xx2 - xx1, 0.f) * fmaxf(yy2 - yy1, 0.f);
                        float iou = __fdiv_rn(inter, ha + (tx2 - tx1) * (ty2 - ty1) - inter);
                        float sv = __uint_as_float(0xFFFFFFFFu - (u32)(s_key[t] >> 32));
                        float sfs = sv * (1.0f - iou);
                        g_cboxes[posG + w] = make_float4(tx1, ty1, tx2, ty2);
                        g_ckeys[posG + w] = makeKey(sfs, hoi, t + 1, c * ROWCAP + w);
                        w++;
                    }
                }
            }
        }
        __threadfence();     // release: only warp 0 wrote globals
    }

    // ---- last-block-done: packed (count, rows) atomic gives nt for free ----
    __syncthreads();
    if (tid == 0) {
        u64 old = atomicAdd(&g_doneTotal, (1ull << 40) | (u64)myTot);
        s_last = ((int)(old >> 40) == NCLS - 1);
        s_nt = (int)(old & 0xFFFFFFFFFFull) + myTot;
    }
    __syncthreads();
    if (!s_last) return;
    __threadfence();   // acquire

    // ================= selection (one block, 1024 threads) =================
    const int nt = s_nt;
    const bool inSm = (nt <= KCAP);

    // prefetch all keys into smem (one parallel RT); init hist
    for (int i = tid; i < nt && i < KCAP; i += NTHR) s_tkeys[i] = g_ckeys[i];
    if (tid < NBUCKET) s_hist[tid] = 0;
    if (tid == 0) { s_ncand = 0; s_cut = NBUCKET - 1; }
    __syncthreads();

    // build histogram from (smem) keys
    for (int i = tid; i < nt; i += NTHR) {
        u64 k = inSm ? s_tkeys[i] : g_ckeys[i];
        atomicAdd(&s_hist[keyBucket(k)], 1);
    }
    __syncthreads();

    if (wid == 0) {    // scores < 1.0 -> bucket >= 127 -> start at group 3
        int acc = 0;
        for (int g = 3; g < NBUCKET / 32; g++) {
            int v = s_hist[g * 32 + lane];
            int scn = v;
            for (int o = 1; o < 32; o <<= 1) {
                int t = __shfl_up_sync(FULL, scn, o);
                if (lane >= o) scn += t;
            }
            unsigned bal = __ballot_sync(FULL, acc + scn >= 100);
            if (bal) { if (lane == 0) s_cut = g * 32 + __ffs(bal) - 1; break; }
            acc += __shfl_sync(FULL, scn, 31);
        }
    }
    __syncthreads();
    const int B = s_cut;

    // collect candidates (smem keys) with warp-aggregated append
    {
        int rounds = (nt + NTHR - 1) / NTHR;
        for (int r = 0; r < rounds; r++) {
            int i = tid + r * NTHR;
            u64 k = 0;
            bool pred = false;
            if (i < nt) {
                k = inSm ? s_tkeys[i] : g_ckeys[i];
                pred = (keyBucket(k) <= B);
            }
            unsigned msk = __ballot_sync(FULL, pred);
            if (msk) {
                int leader = __ffs(msk) - 1;
                int base = 0;
                if (lane == leader) base = atomicAdd(&s_ncand, __popc(msk));
                base = __shfl_sync(FULL, base, leader);
                if (pred) {
                    int p = base + __popc(msk & ((1u << lane) - 1u));
                    if (p < CANDCAP) { s_cand[p] = k; s_cidx[p] = i; }
                }
            }
        }
    }
    __syncthreads();
    int nc = s_ncand; if (nc > CANDCAP) nc = CANDCAP;

    // fused rank-compute -> direct output; candidate box load overlaps rank
    if (tid < nc) {
        u64 k = s_cand[tid];
        float4 bx = g_cboxes[s_cidx[tid]];     // issued before rank loop
        int rank = 0;
        for (int j = 0; j < nc; j++) rank += (s_cand[j] < k);
        if (rank < 100) {
            int ref = (int)(k & 0x3FFFull);
            float lb = (float)(ref / ROWCAP);                          // exact label
            float scr = __uint_as_float(0xFFFFFFFFu - (u32)(k >> 32)); // exact score
            float o2 = lb * mc;
            out[rank * 4 + 0] = bx.x - o2;
            out[rank * 4 + 1] = bx.y - o2;
            out[rank * 4 + 2] = bx.z - o2;
            out[rank * 4 + 3] = bx.w - o2;
            out[400 + rank] = scr;
            out[500 + rank] = lb;
        }
    } else if (tid < 100) {      // ranks that cannot exist: zero-fill
        out[tid * 4 + 0] = 0.f; out[tid * 4 + 1] = 0.f;
        out[tid * 4 + 2] = 0.f; out[tid * 4 + 3] = 0.f;
        out[400 + tid] = 0.f;
        out[500 + tid] = 0.f;
    }

    // reset globals for next graph replay
    __syncthreads();
    if (tid == 0) { g_total = 0; g_doneTotal = 0; }
}

extern "C" void kernel_launch(void* const* d_in, const int* in_sizes, int n_in,
                              void* d_out, int out_size) {
    const float* boxes  = (const float*)d_in[0];
    const float* scores = (const float*)d_in[1];
    const int*   labels = (const int*)d_in[2];
    float* out = (float*)d_out;

    k_fused<<<NCLS, NTHR>>>(boxes, scores, labels, out);
}

// round 16
// speedup vs baseline: 1.1542x; 1.1343x over previous
#include <cuda_runtime.h>
#include <cstdint>

#define NBOX   2048
#define NCLS   80
#define NTHR   1024
#define PC     64           // per-class box cap (P(Binom(2048,1/80)>64) ~ 1e-11)
#define ROWCAP 128          // rows per class <= 2*PC
#define VOTE_TH  0.65f
#define SOFT_THR 0.05f
#define CANDCAP  512
#define NBUCKET  1024

typedef unsigned long long u64;
typedef unsigned int u32;

__device__ float4 g_cboxes[NCLS * ROWCAP];  // compact box buffer (offset coords)
__device__ u64    g_ckeys[NCLS * ROWCAP];   // compact key buffer
__device__ int    g_hist[NBUCKET];
__device__ int    g_total = 0;              // row allocator
__device__ u64    g_doneTotal = 0;          // (blocks_done << 40) | rows_done

// Key (ascending = output order): score desc (32b inverted float bits, exact
// & invertible), head original index asc (11b), within-cluster slot (7b),
// row ref = class*ROWCAP+slot (14b; also encodes the class/label).
__device__ __forceinline__ u64 makeKey(float score, int headIdx, int within, int ref) {
    u64 u = (u64)(0xFFFFFFFFu - __float_as_uint(score));
    return (u << 32) | ((u64)headIdx << 21) | ((u64)within << 14) | (u64)ref;
}

__device__ __forceinline__ int keyBucket(u64 k) {
    u32 inv = (u32)(k >> 32);
    int bkt = (int)((inv - 0xC0000000u) >> 16);
    return bkt > (NBUCKET - 1) ? (NBUCKET - 1) : (bkt < 0 ? 0 : bkt);
}

// Exactly replicates (__fdiv_rn(inter, u) >= VOTE_TH) without dividing in the
// common case; the +-4e-7 band covers all quotient-rounding ambiguity.
__device__ __forceinline__ bool mergePred(float inter, float u) {
    float t = VOTE_TH * u;
    if (inter > t * 1.0000006f) return true;
    if (inter < t * 0.9999994f) return false;
    return __fdiv_rn(inter, u) >= VOTE_TH;
}

__global__ __launch_bounds__(NTHR) void k_fused(const float* __restrict__ boxes,
                                                const float* __restrict__ scores,
                                                const int*   __restrict__ labels,
                                                float* __restrict__ out) {
    const int c = blockIdx.x, tid = threadIdx.x;
    const int wid = tid >> 5, lane = tid & 31;
    const unsigned FULL = 0xFFFFFFFFu;

    __shared__ float s_max[NTHR / 32];
    __shared__ int   s_n, s_pos, s_last, s_nt;
    __shared__ u64   s_key[PC];      // unsorted slot order
    __shared__ float4 s_bx[PC];      // raw coords, unsorted slot order
    __shared__ u64   s_adj[PC];      // IoU>=0.65 adjacency (slot-space bits)
    __shared__ u64   s_blw[PC];      // below[r] = {j : key[j] < key[r]}
    __shared__ int   s_ch[PC];
    __shared__ u64   s_cm[PC], s_sm[PC];
    __shared__ float4 s_b0[PC];      // voted head boxes
    __shared__ int   s_rc[PC + 1];
    // selection (last block only)
    __shared__ int   s_hist[NBUCKET];
    __shared__ u64   s_cand[CANDCAP];
    __shared__ int   s_cidx[CANDCAP];
    __shared__ int   s_cut, s_ncand;

    // ---- Phase A: issue ALL global loads first (independent, one RT) ----
    const float4* b4 = (const float4*)boxes;
    float4 v0 = b4[tid];
    float4 v1 = b4[tid + NTHR];
    int   l0 = labels[tid],        l1 = labels[tid + NTHR];
    float f0 = scores[tid],        f1 = scores[tid + NTHR];

    if (tid == 0) s_n = 0;
    if (tid < PC) { s_adj[tid] = 0; s_blw[tid] = 0; s_cm[tid] = 0; }
    __syncthreads();

    float m = fmaxf(fmaxf(fmaxf(v0.x, v0.y), fmaxf(v0.z, v0.w)),
                    fmaxf(fmaxf(v1.x, v1.y), fmaxf(v1.z, v1.w)));
    if (l0 == c) { int p = atomicAdd(&s_n, 1); if (p < PC) { s_key[p] = ((u64)(0xFFFFFFFFu - __float_as_uint(f0)) << 32) | (u32)tid;          s_bx[p] = v0; } }
    if (l1 == c) { int p = atomicAdd(&s_n, 1); if (p < PC) { s_key[p] = ((u64)(0xFFFFFFFFu - __float_as_uint(f1)) << 32) | (u32)(tid + NTHR); s_bx[p] = v1; } }

    for (int o = 16; o; o >>= 1) m = fmaxf(m, __shfl_xor_sync(FULL, m, o));
    if (lane == 0) s_max[wid] = m;
    __syncthreads();

    float mc = s_max[0];
#pragma unroll
    for (int w = 1; w < NTHR / 32; w++) mc = fmaxf(mc, s_max[w]);
    mc += 1.0f;   // exact max -> identical in every block

    const int n = (s_n > PC) ? PC : s_n;
    const float off = (float)c * mc;

    // ---- Phase C': fused adjacency + below-mask, 16 threads per row ----
    {
        int r = tid >> 4, q = tid & 15;
        if (r < n) {
            u64 kr = s_key[r];
            float4 br = s_bx[r];
            float rx1 = br.x + off, ry1 = br.y + off, rx2 = br.z + off, ry2 = br.w + off;
            float ra = (rx2 - rx1) * (ry2 - ry1);
            int j0 = q * 4, j1 = j0 + 4; if (j1 > n) j1 = n;
            u64 abits = 0, bbits = 0;
            for (int j = j0; j < j1; j++) {
                u64 kj = s_key[j];
                float4 bj = s_bx[j];
                float jx1 = bj.x + off, jy1 = bj.y + off, jx2 = bj.z + off, jy2 = bj.w + off;
                float xx1 = fmaxf(rx1, jx1);
                float yy1 = fmaxf(ry1, jy1);
                float xx2 = fminf(rx2, jx2);
                float yy2 = fminf(ry2, jy2);
                float inter = fmaxf(xx2 - xx1, 0.f) * fmaxf(yy2 - yy1, 0.f);
                float ua = ra + (jx2 - jx1) * (jy2 - jy1) - inter;
                if (mergePred(inter, ua)) abits |= 1ull << j;
                if (kj < kr)              bbits |= 1ull << j;
            }
            if (abits) atomicOr(&s_adj[r], abits);
            if (bbits) atomicOr(&s_blw[r], bbits);
        }
    }
    __syncthreads();

    // ======== Phases D..G entirely in warp 0 (2 rows / 2 clusters per lane) ====
    int myTot = 0;
    if (wid == 0) {
        const int r0i = lane, r1i = lane + 32;
        u64 a0 = s_adj[r0i], a1 = s_adj[r1i];
        u64 bl0 = s_blw[r0i], bl1 = s_blw[r1i];
        const u64 validMask = (n >= 64) ? ~0ull : ((1ull << n) - 1ull);
        const bool val0 = r0i < n, val1 = r1i < n;

        // ---- D1: fixpoint head-set iteration (key-order below masks) ----
        u64 head = validMask;
        for (int it = 0; it < 64; it++) {
            bool b0 = val0 && ((a0 & head & bl0) == 0);
            bool b1 = val1 && ((a1 & head & bl1) == 0);
            u64 nh = (u64)__ballot_sync(FULL, b0) | ((u64)__ballot_sync(FULL, b1) << 32);
            if (nh == head) break;
            head = nh;
        }

        // ---- D2: cluster assignment (owner = argmin-key adjacent head) ----
#pragma unroll
        for (int e = 0; e < 2; e++) {
            int r = lane + e * 32;
            if (r < n) {
                u64 cand = (e ? a1 : a0) & head;   // nonempty (self-adjacency)
                int h = __ffsll((long long)cand) - 1;
                u64 bk = s_key[h];
                u64 t2 = cand & (cand - 1);
                while (t2) {
                    int j = __ffsll((long long)t2) - 1; t2 &= t2 - 1;
                    u64 kj = s_key[j];
                    if (kj < bk) { bk = kj; h = j; }
                }
                int ci = __popcll(head & s_blw[h]);  // clusters in key order
                atomicOr(&s_cm[ci], 1ull << r);
                if (h == r) s_ch[ci] = r;
            }
        }
        const int ncl = __popcll(head);
        __syncwarp();

        // ---- E: per-cluster head row + soft mask/count (2 clusters per lane) ----
        float hsA[2];
#pragma unroll
        for (int e = 0; e < 2; e++) {
            int ci = lane + e * 32;
            if (ci < ncl) {
                int h = s_ch[ci];
                u64 mg = s_cm[ci];
                int nm = __popcll(mg);
                hsA[e] = __uint_as_float(0xFFFFFFFFu - (u32)(s_key[h] >> 32));

                float wsum = 0.f, w0 = 0.f, w1 = 0.f, w2 = 0.f, w3 = 0.f;
                u64 mm = mg;
                while (mm) {
                    int t = __ffsll((long long)mm) - 1; mm &= mm - 1;
                    float sv = __uint_as_float(0xFFFFFFFFu - (u32)(s_key[t] >> 32));
                    float4 bt = s_bx[t];
                    wsum += sv;
                    w0 += (bt.x + off) * sv; w1 += (bt.y + off) * sv;
                    w2 += (bt.z + off) * sv; w3 += (bt.w + off) * sv;
                }
                float wsafe = (wsum > 0.f) ? wsum : 1.f;
                s_b0[ci] = make_float4(__fdiv_rn(w0, wsafe), __fdiv_rn(w1, wsafe),
                                       __fdiv_rn(w2, wsafe), __fdiv_rn(w3, wsafe));

                u64 soft = 0; int cnt = 1;
                if (nm > 1) {
                    float4 bh = s_bx[h];
                    float hx1 = bh.x + off, hy1 = bh.y + off, hx2 = bh.z + off, hy2 = bh.w + off;
                    float ha = (hx2 - hx1) * (hy2 - hy1);
                    mm = mg;
                    while (mm) {
                        int t = __ffsll((long long)mm) - 1; mm &= mm - 1;
                        float4 bt = s_bx[t];
                        float tx1 = bt.x + off, ty1 = bt.y + off, tx2 = bt.z + off, ty2 = bt.w + off;
                        float xx1 = fmaxf(hx1, tx1);
                        float yy1 = fmaxf(hy1, ty1);
                        float xx2 = fminf(hx2, tx2);
                        float yy2 = fminf(hy2, ty2);
                        float inter = fmaxf(xx2 - xx1, 0.f) * fmaxf(yy2 - yy1, 0.f);
                        float iou = __fdiv_rn(inter, ha + (tx2 - tx1) * (ty2 - ty1) - inter);
                        float sv = __uint_as_float(0xFFFFFFFFu - (u32)(s_key[t] >> 32));
                        float sfs = sv * (1.0f - iou);
                        if (sfs >= SOFT_THR) { soft |= 1ull << t; cnt++; }
                    }
                }
                s_sm[ci] = soft;
                s_rc[ci] = cnt;
            }
        }
        __syncwarp();

        // ---- F: warp exclusive scan of cluster row counts + global append pos ----
        {
            int v0i = (lane < ncl) ? s_rc[lane] : 0;
            int v1i = (lane + 32 < ncl) ? s_rc[lane + 32] : 0;
            int sa0 = v0i, sa1 = v1i;
            for (int o = 1; o < 32; o <<= 1) {
                int t = __shfl_up_sync(FULL, sa0, o); if (lane >= o) sa0 += t;
                int u = __shfl_up_sync(FULL, sa1, o); if (lane >= o) sa1 += u;
            }
            int tot0 = __shfl_sync(FULL, sa0, 31);
            int tot  = tot0 + __shfl_sync(FULL, sa1, 31);
            if (lane < ncl) s_rc[lane] = sa0 - v0i;
            if (lane + 32 < ncl) s_rc[lane + 32] = tot0 + sa1 - v1i;
            if (lane == 0) { s_pos = atomicAdd(&g_total, tot); myTot = tot; }
        }
        __syncwarp();
        const int posG = s_pos;

        // ---- G: parallel emission of boxes + keys + global histogram ----
#pragma unroll
        for (int e = 0; e < 2; e++) {
            int ci = lane + e * 32;
            if (ci < ncl) {
                int h = s_ch[ci];
                int hoi = (int)(s_key[h] & 0x7FFull);
                int ofs = s_rc[ci];
                int slot = c * ROWCAP + ofs;
                g_cboxes[posG + ofs] = s_b0[ci];
                u64 hk = makeKey(hsA[e], hoi, 0, slot);
                g_ckeys[posG + ofs] = hk;
                atomicAdd(&g_hist[keyBucket(hk)], 1);

                u64 mm = s_sm[ci];
                if (mm) {
                    float4 bh = s_bx[h];
                    float hx1 = bh.x + off, hy1 = bh.y + off, hx2 = bh.z + off, hy2 = bh.w + off;
                    float ha = (hx2 - hx1) * (hy2 - hy1);
                    int w = ofs + 1;
                    while (mm) {
                        int t = __ffsll((long long)mm) - 1; mm &= mm - 1;
                        float4 bt = s_bx[t];
                        float tx1 = bt.x + off, ty1 = bt.y + off, tx2 = bt.z + off, ty2 = bt.w + off;
                        float xx1 = fmaxf(hx1, tx1);
                        float yy1 = fmaxf(hy1, ty1);
                        float xx2 = fminf(hx2, tx2);
                        float yy2 = fminf(hy2, ty2);
                        float inter = fmaxf(xx2 - xx1, 0.f) * fmaxf(yy2 - yy1, 0.f);
                        float iou = __fdiv_rn(inter, ha + (tx2 - tx1) * (ty2 - ty1) - inter);
                        float sv = __uint_as_float(0xFFFFFFFFu - (u32)(s_key[t] >> 32));
                        float sfs = sv * (1.0f - iou);
                        g_cboxes[posG + w] = make_float4(tx1, ty1, tx2, ty2);
                        u64 sk = makeKey(sfs, hoi, t + 1, c * ROWCAP + w);
                        g_ckeys[posG + w] = sk;
                        atomicAdd(&g_hist[keyBucket(sk)], 1);
                        w++;
                    }
                }
            }
        }
        __threadfence();     // release: only warp 0 wrote globals
    }

    // ---- last-block-done: packed (count, rows) atomic gives nt for free ----
    __syncthreads();
    if (tid == 0) {
        u64 old = atomicAdd(&g_doneTotal, (1ull << 40) | (u64)myTot);
        s_last = ((int)(old >> 40) == NCLS - 1);
        s_nt = (int)(old & 0xFFFFFFFFFFull) + myTot;
    }
    __syncthreads();
    if (!s_last) return;
    __threadfence();   // acquire

    // ================= selection (one block, 1024 threads) =================
    const int nt = s_nt;

    // global histogram was built by all blocks during Phase G (off-path)
    if (tid < NBUCKET) s_hist[tid] = g_hist[tid];
    if (tid == 0) { s_ncand = 0; s_cut = NBUCKET - 1; }
    __syncthreads();

    if (wid == 0) {    // scores < 1.0 -> bucket >= 127 -> start at group 3
        int acc = 0;
        for (int g = 3; g < NBUCKET / 32; g++) {
            int v = s_hist[g * 32 + lane];
            int scn = v;
            for (int o = 1; o < 32; o <<= 1) {
                int t = __shfl_up_sync(FULL, scn, o);
                if (lane >= o) scn += t;
            }
            unsigned bal = __ballot_sync(FULL, acc + scn >= 100);
            if (bal) { if (lane == 0) s_cut = g * 32 + __ffs(bal) - 1; break; }
            acc += __shfl_sync(FULL, scn, 31);
        }
    }
    __syncthreads();
    const int B = s_cut;

    // collect candidates with warp-aggregated append
    {
        int rounds = (nt + NTHR - 1) / NTHR;
        for (int r = 0; r < rounds; r++) {
            int i = tid + r * NTHR;
            u64 k = 0;
            bool pred = false;
            if (i < nt) {
                k = g_ckeys[i];
                pred = (keyBucket(k) <= B);
            }
            unsigned msk = __ballot_sync(FULL, pred);
            if (msk) {
                int leader = __ffs(msk) - 1;
                int base = 0;
                if (lane == leader) base = atomicAdd(&s_ncand, __popc(msk));
                base = __shfl_sync(FULL, base, leader);
                if (pred) {
                    int p = base + __popc(msk & ((1u << lane) - 1u));
                    if (p < CANDCAP) { s_cand[p] = k; s_cidx[p] = i; }
                }
            }
        }
    }
    __syncthreads();
    int nc = s_ncand; if (nc > CANDCAP) nc = CANDCAP;

    // fused rank-compute -> direct output; candidate box load overlaps rank
    if (tid < nc) {
        u64 k = s_cand[tid];
        float4 bx = g_cboxes[s_cidx[tid]];     // issued before rank loop
        int rank = 0;
        for (int j = 0; j < nc; j++) rank += (s_cand[j] < k);
        if (rank < 100) {
            int ref = (int)(k & 0x3FFFull);
            float lb = (float)(ref / ROWCAP);                          // exact label
            float scr = __uint_as_float(0xFFFFFFFFu - (u32)(k >> 32)); // exact score
            float o2 = lb * mc;
            out[rank * 4 + 0] = bx.x - o2;
            out[rank * 4 + 1] = bx.y - o2;
            out[rank * 4 + 2] = bx.z - o2;
            out[rank * 4 + 3] = bx.w - o2;
            out[400 + rank] = scr;
            out[500 + rank] = lb;
        }
    } else if (tid < 100) {      // ranks that cannot exist: zero-fill
        out[tid * 4 + 0] = 0.f; out[tid * 4 + 1] = 0.f;
        out[tid * 4 + 2] = 0.f; out[tid * 4 + 3] = 0.f;
        out[400 + tid] = 0.f;
        out[500 + tid] = 0.f;
    }

    // reset globals for next graph replay
    if (tid < NBUCKET) g_hist[tid] = 0;
    __syncthreads();
    if (tid == 0) { g_total = 0; g_doneTotal = 0; }
}

extern "C" void kernel_launch(void* const* d_in, const int* in_sizes, int n_in,
                              void* d_out, int out_size) {
    const float* boxes  = (const float*)d_in[0];
    const float* scores = (const float*)d_in[1];
    const int*   labels = (const int*)d_in[2];
    float* out = (float*)d_out;

    k_fused<<<NCLS, NTHR>>>(boxes, scores, labels, out);
}